// round 1
// baseline (speedup 1.0000x reference)
#include <cuda_runtime.h>

#define NUSER 100000
#define NITEM 50000
#define NEDGE 2000000
#define DIM   64
#define NLAYERS 3

// ---------------- scratch (device globals: allocation-free rule) ----------------
__device__ float g_user_e[NUSER * DIM];   // current user layer embedding
__device__ float g_item_e[NITEM * DIM];   // current item layer embedding
__device__ float g_acc_u[NUSER * DIM];    // scatter accumulator (user rows)
__device__ float g_acc_i[NITEM * DIM];    // scatter accumulator (item rows)
__device__ float g_deg_u[NUSER];
__device__ float g_deg_i[NITEM];
__device__ float g_nu_inv[NUSER];         // 1/d_u
__device__ float g_nu_is [NUSER];         // d_u^-1/2
__device__ float g_ni_inv[NITEM];         // 1/d_i
__device__ float g_ni_is [NITEM];         // d_i^-1/2

// ---------------- kernels ----------------

__global__ void count_degrees(const int* __restrict__ u_idx,
                              const int* __restrict__ i_idx,
                              float* __restrict__ deg_u,
                              float* __restrict__ deg_i) {
    int t = blockIdx.x * blockDim.x + threadIdx.x;
    if (t >= NEDGE) return;
    atomicAdd(deg_u + __ldg(u_idx + t), 1.0f);
    atomicAdd(deg_i + __ldg(i_idx + t), 1.0f);
}

__global__ void compute_norms(const float* __restrict__ deg,
                              float* __restrict__ inv,
                              float* __restrict__ invsqrt, int n) {
    int t = blockIdx.x * blockDim.x + threadIdx.x;
    if (t >= n) return;
    float d = deg[t];
    d = (d == 0.0f) ? 1.0f : d;
    inv[t]     = 1.0f / d;
    invsqrt[t] = rsqrtf(d);
}

// dst[didx[e]] += src[sidx[e]] * scale[sidx[e]]   (edge-parallel, 16 threads/edge)
__global__ void __launch_bounds__(256)
spmm_scatter(const float* __restrict__ src,
             const float* __restrict__ scale,
             const int*   __restrict__ sidx,
             const int*   __restrict__ didx,
             float*       __restrict__ dst) {
    int t = blockIdx.x * blockDim.x + threadIdx.x;
    int e = t >> 4;
    if (e >= NEDGE) return;
    int c = t & 15;
    int s = __ldg(sidx + e);
    int d = __ldg(didx + e);
    float sc = __ldg(scale + s);
    float4 v = __ldg(reinterpret_cast<const float4*>(src) + s * 16 + c);
    v.x *= sc; v.y *= sc; v.z *= sc; v.w *= sc;
    float* p = dst + (size_t)d * DIM + c * 4;
    asm volatile("red.global.add.v4.f32 [%0], {%1,%2,%3,%4};"
                 :: "l"(p), "f"(v.x), "f"(v.y), "f"(v.z), "f"(v.w)
                 : "memory");
}

// e_out = acc * is[row];  sum += e_out     (vectorized float4)
__global__ void scale_and_accum(const float4* __restrict__ acc,
                                const float*  __restrict__ is,
                                float4* __restrict__ e_out,
                                float4* __restrict__ sum, int rows) {
    int t = blockIdx.x * blockDim.x + threadIdx.x;
    if (t >= rows * 16) return;
    int r = t >> 4;
    float s = __ldg(is + r);
    float4 v = acc[t];
    v.x *= s; v.y *= s; v.z *= s; v.w *= s;
    e_out[t] = v;
    float4 a = sum[t];
    a.x += v.x; a.y += v.y; a.z += v.z; a.w += v.w;
    sum[t] = a;
}

__global__ void final_scale(float4* __restrict__ out, int n4) {
    int t = blockIdx.x * blockDim.x + threadIdx.x;
    if (t >= n4) return;
    const float k = 1.0f / (NLAYERS + 1);
    float4 v = out[t];
    v.x *= k; v.y *= k; v.z *= k; v.w *= k;
    out[t] = v;
}

// ---------------- launch ----------------

extern "C" void kernel_launch(void* const* d_in, const int* in_sizes, int n_in,
                              void* d_out, int out_size) {
    const float* user_emb = (const float*)d_in[0];
    const float* item_emb = (const float*)d_in[1];
    const int*   u_idx    = (const int*)d_in[2];
    const int*   i_idx    = (const int*)d_in[3];
    float* out = (float*)d_out;
    float* sum_u = out;                 // [NUSER*DIM]
    float* sum_i = out + NUSER * DIM;   // [NITEM*DIM]

    // resolve device-global addresses (query only — capture-safe)
    float *p_user_e, *p_item_e, *p_acc_u, *p_acc_i;
    float *p_deg_u, *p_deg_i, *p_nu_inv, *p_nu_is, *p_ni_inv, *p_ni_is;
    cudaGetSymbolAddress((void**)&p_user_e, g_user_e);
    cudaGetSymbolAddress((void**)&p_item_e, g_item_e);
    cudaGetSymbolAddress((void**)&p_acc_u,  g_acc_u);
    cudaGetSymbolAddress((void**)&p_acc_i,  g_acc_i);
    cudaGetSymbolAddress((void**)&p_deg_u,  g_deg_u);
    cudaGetSymbolAddress((void**)&p_deg_i,  g_deg_i);
    cudaGetSymbolAddress((void**)&p_nu_inv, g_nu_inv);
    cudaGetSymbolAddress((void**)&p_nu_is,  g_nu_is);
    cudaGetSymbolAddress((void**)&p_ni_inv, g_ni_inv);
    cudaGetSymbolAddress((void**)&p_ni_is,  g_ni_is);

    const int TB = 256;
    const int EDGE_BLKS  = (NEDGE + TB - 1) / TB;
    const int SPMM_BLKS  = (NEDGE * 16 + TB - 1) / TB;
    const int U_ROW_BLKS = (NUSER * 16 + TB - 1) / TB;
    const int I_ROW_BLKS = (NITEM * 16 + TB - 1) / TB;

    // degrees + norms
    cudaMemsetAsync(p_deg_u, 0, NUSER * sizeof(float), 0);
    cudaMemsetAsync(p_deg_i, 0, NITEM * sizeof(float), 0);
    count_degrees<<<EDGE_BLKS, TB>>>(u_idx, i_idx, p_deg_u, p_deg_i);
    compute_norms<<<(NUSER + TB - 1) / TB, TB>>>(p_deg_u, p_nu_inv, p_nu_is, NUSER);
    compute_norms<<<(NITEM + TB - 1) / TB, TB>>>(p_deg_i, p_ni_inv, p_ni_is, NITEM);

    // init layer state + running sums
    cudaMemcpyAsync(p_user_e, user_emb, NUSER * DIM * sizeof(float),
                    cudaMemcpyDeviceToDevice, 0);
    cudaMemcpyAsync(p_item_e, item_emb, NITEM * DIM * sizeof(float),
                    cudaMemcpyDeviceToDevice, 0);
    cudaMemcpyAsync(sum_u, user_emb, NUSER * DIM * sizeof(float),
                    cudaMemcpyDeviceToDevice, 0);
    cudaMemcpyAsync(sum_i, item_emb, NITEM * DIM * sizeof(float),
                    cudaMemcpyDeviceToDevice, 0);

    for (int layer = 0; layer < NLAYERS; ++layer) {
        // ---- user propagation: u -> items -> u ----
        // acc_i[i] += user_e[u] * d_u^-1/2
        cudaMemsetAsync(p_acc_i, 0, NITEM * DIM * sizeof(float), 0);
        spmm_scatter<<<SPMM_BLKS, TB>>>(p_user_e, p_nu_is, u_idx, i_idx, p_acc_i);
        // acc_u[u] += acc_i[i] * d_i^-1
        cudaMemsetAsync(p_acc_u, 0, NUSER * DIM * sizeof(float), 0);
        spmm_scatter<<<SPMM_BLKS, TB>>>(p_acc_i, p_ni_inv, i_idx, u_idx, p_acc_u);
        // user_e = acc_u * d_u^-1/2 ; sum_u += user_e
        scale_and_accum<<<U_ROW_BLKS, TB>>>((const float4*)p_acc_u, p_nu_is,
                                            (float4*)p_user_e, (float4*)sum_u, NUSER);

        // ---- item propagation: i -> users -> i ----
        // acc_u[u] += item_e[i] * d_i^-1/2
        cudaMemsetAsync(p_acc_u, 0, NUSER * DIM * sizeof(float), 0);
        spmm_scatter<<<SPMM_BLKS, TB>>>(p_item_e, p_ni_is, i_idx, u_idx, p_acc_u);
        // acc_i[i] += acc_u[u] * d_u^-1
        cudaMemsetAsync(p_acc_i, 0, NITEM * DIM * sizeof(float), 0);
        spmm_scatter<<<SPMM_BLKS, TB>>>(p_acc_u, p_nu_inv, u_idx, i_idx, p_acc_i);
        // item_e = acc_i * d_i^-1/2 ; sum_i += item_e
        scale_and_accum<<<I_ROW_BLKS, TB>>>((const float4*)p_acc_i, p_ni_is,
                                            (float4*)p_item_e, (float4*)sum_i, NITEM);
    }

    // out *= 1/(NLAYERS+1)
    const int N4 = (NUSER + NITEM) * DIM / 4;
    final_scale<<<(N4 + TB - 1) / TB, TB>>>((float4*)out, N4);
}

// round 2
// speedup vs baseline: 2.2413x; 2.2413x over previous
#include <cuda_runtime.h>

#define NUSER 100000
#define NITEM 50000
#define NEDGE 2000000
#define DIM   64
#define NLAYERS 3
#define SB    1024   // scan block size

// ---------------- scratch (device globals: allocation-free rule) ----------------
__device__ float g_user_e[NUSER * DIM];
__device__ float g_item_e[NITEM * DIM];
__device__ float g_acc_u[NUSER * DIM];
__device__ float g_acc_i[NITEM * DIM];
__device__ int   g_cnt_u[NUSER];
__device__ int   g_cnt_i[NITEM];
__device__ int   g_rowptr_u[NUSER + 1];
__device__ int   g_rowptr_i[NITEM + 1];
__device__ int   g_cur_u[NUSER];
__device__ int   g_cur_i[NITEM];
__device__ int   g_cols_u[NEDGE];   // for user rows: item neighbor ids
__device__ int   g_cols_i[NEDGE];   // for item rows: user neighbor ids
__device__ int   g_bsums_u[128];
__device__ int   g_bsums_i[128];
__device__ float g_nu_inv[NUSER];
__device__ float g_nu_is [NUSER];
__device__ float g_ni_inv[NITEM];
__device__ float g_ni_is [NITEM];

// ---------------- CSR build ----------------

__global__ void hist_degrees(const int* __restrict__ u_idx,
                             const int* __restrict__ i_idx,
                             int* __restrict__ cnt_u,
                             int* __restrict__ cnt_i) {
    int t = blockIdx.x * blockDim.x + threadIdx.x;
    if (t >= NEDGE) return;
    atomicAdd(cnt_u + __ldg(u_idx + t), 1);
    atomicAdd(cnt_i + __ldg(i_idx + t), 1);
}

// per-block exclusive scan; bsums[b] = block total
__global__ void scan_block(const int* __restrict__ in, int* __restrict__ out,
                           int* __restrict__ bsums, int n) {
    __shared__ int sh[SB];
    int gid = blockIdx.x * SB + threadIdx.x;
    int v = (gid < n) ? in[gid] : 0;
    sh[threadIdx.x] = v;
    __syncthreads();
    for (int off = 1; off < SB; off <<= 1) {
        int t = (threadIdx.x >= off) ? sh[threadIdx.x - off] : 0;
        __syncthreads();
        sh[threadIdx.x] += t;
        __syncthreads();
    }
    if (gid < n) out[gid] = sh[threadIdx.x] - v;      // exclusive
    if (threadIdx.x == SB - 1) bsums[blockIdx.x] = sh[SB - 1];
}

// exclusive scan of up to 128 block sums, in place (single block of 128)
__global__ void scan_small(int* __restrict__ data, int n) {
    __shared__ int sh[128];
    int v = (threadIdx.x < n) ? data[threadIdx.x] : 0;
    sh[threadIdx.x] = v;
    __syncthreads();
    for (int off = 1; off < 128; off <<= 1) {
        int t = (threadIdx.x >= off) ? sh[threadIdx.x - off] : 0;
        __syncthreads();
        sh[threadIdx.x] += t;
        __syncthreads();
    }
    if (threadIdx.x < n) data[threadIdx.x] = sh[threadIdx.x] - v;
}

__global__ void add_offsets(int* __restrict__ out, const int* __restrict__ bsums, int n) {
    int gid = blockIdx.x * SB + threadIdx.x;
    if (gid < n) out[gid] += bsums[blockIdx.x];
    if (gid == 0) out[n] = NEDGE;   // rowptr[n] = total edges
}

__global__ void fill_csr(const int* __restrict__ u_idx, const int* __restrict__ i_idx,
                         int* __restrict__ cur_u, int* __restrict__ cur_i,
                         int* __restrict__ cols_u, int* __restrict__ cols_i) {
    int e = blockIdx.x * blockDim.x + threadIdx.x;
    if (e >= NEDGE) return;
    int u = __ldg(u_idx + e);
    int i = __ldg(i_idx + e);
    int pu = atomicAdd(cur_u + u, 1);
    cols_u[pu] = i;
    int pi = atomicAdd(cur_i + i, 1);
    cols_i[pi] = u;
}

__global__ void compute_norms(const int* __restrict__ cnt,
                              float* __restrict__ inv,
                              float* __restrict__ invsqrt, int n) {
    int t = blockIdx.x * blockDim.x + threadIdx.x;
    if (t >= n) return;
    float d = (float)cnt[t];
    d = (d == 0.0f) ? 1.0f : d;
    inv[t]     = 1.0f / d;
    invsqrt[t] = rsqrtf(d);
}

// ---------------- pull-mode SpMM ----------------
// dst[r] = (outscale ? outscale[r] : 1) * sum_{k in row r} srcscale[col[k]] * src[col[k]]
// if sum != null:  sum[r] += dst[r]
// 16 threads per row (one float4 per lane). Index/scale loads staged cooperatively.
__global__ void __launch_bounds__(256)
spmm_pull(const float4* __restrict__ src,
          const float*  __restrict__ srcscale,
          const int*    __restrict__ rowptr,
          const int*    __restrict__ cols,
          const float*  __restrict__ outscale,
          float4*       __restrict__ dst,
          float4*       __restrict__ sum,
          int nrows) {
    int t = blockIdx.x * blockDim.x + threadIdx.x;
    int r = t >> 4;
    if (r >= nrows) return;
    int c = t & 15;
    unsigned hmask = 0xFFFFu << (threadIdx.x & 16);   // this half-warp's lanes

    int beg = __ldg(rowptr + r);
    int end = __ldg(rowptr + r + 1);

    float4 acc = make_float4(0.f, 0.f, 0.f, 0.f);
    for (int base = beg; base < end; base += 16) {
        int myi = base + c;
        int   mycol = 0;
        float mys   = 0.f;
        if (myi < end) {
            mycol = __ldg(cols + myi);
            mys   = __ldg(srcscale + mycol);
        }
        int cnt = min(16, end - base);
        #pragma unroll 4
        for (int j = 0; j < cnt; ++j) {
            int   col = __shfl_sync(hmask, mycol, j, 16);
            float s   = __shfl_sync(hmask, mys,   j, 16);
            float4 v  = __ldg(src + col * 16 + c);
            acc.x += s * v.x; acc.y += s * v.y;
            acc.z += s * v.z; acc.w += s * v.w;
        }
    }
    if (outscale) {
        float os = __ldg(outscale + r);
        acc.x *= os; acc.y *= os; acc.z *= os; acc.w *= os;
    }
    dst[t] = acc;
    if (sum) {
        float4 a = sum[t];
        a.x += acc.x; a.y += acc.y; a.z += acc.z; a.w += acc.w;
        sum[t] = a;
    }
}

__global__ void final_scale(float4* __restrict__ out, int n4) {
    int t = blockIdx.x * blockDim.x + threadIdx.x;
    if (t >= n4) return;
    const float k = 1.0f / (NLAYERS + 1);
    float4 v = out[t];
    v.x *= k; v.y *= k; v.z *= k; v.w *= k;
    out[t] = v;
}

// ---------------- launch ----------------

extern "C" void kernel_launch(void* const* d_in, const int* in_sizes, int n_in,
                              void* d_out, int out_size) {
    const float* user_emb = (const float*)d_in[0];
    const float* item_emb = (const float*)d_in[1];
    const int*   u_idx    = (const int*)d_in[2];
    const int*   i_idx    = (const int*)d_in[3];
    float* out = (float*)d_out;
    float* sum_u = out;
    float* sum_i = out + NUSER * DIM;

    float *p_user_e, *p_item_e, *p_acc_u, *p_acc_i;
    float *p_nu_inv, *p_nu_is, *p_ni_inv, *p_ni_is;
    int *p_cnt_u, *p_cnt_i, *p_rp_u, *p_rp_i, *p_cur_u, *p_cur_i;
    int *p_cols_u, *p_cols_i, *p_bs_u, *p_bs_i;
    cudaGetSymbolAddress((void**)&p_user_e, g_user_e);
    cudaGetSymbolAddress((void**)&p_item_e, g_item_e);
    cudaGetSymbolAddress((void**)&p_acc_u,  g_acc_u);
    cudaGetSymbolAddress((void**)&p_acc_i,  g_acc_i);
    cudaGetSymbolAddress((void**)&p_nu_inv, g_nu_inv);
    cudaGetSymbolAddress((void**)&p_nu_is,  g_nu_is);
    cudaGetSymbolAddress((void**)&p_ni_inv, g_ni_inv);
    cudaGetSymbolAddress((void**)&p_ni_is,  g_ni_is);
    cudaGetSymbolAddress((void**)&p_cnt_u,  g_cnt_u);
    cudaGetSymbolAddress((void**)&p_cnt_i,  g_cnt_i);
    cudaGetSymbolAddress((void**)&p_rp_u,   g_rowptr_u);
    cudaGetSymbolAddress((void**)&p_rp_i,   g_rowptr_i);
    cudaGetSymbolAddress((void**)&p_cur_u,  g_cur_u);
    cudaGetSymbolAddress((void**)&p_cur_i,  g_cur_i);
    cudaGetSymbolAddress((void**)&p_cols_u, g_cols_u);
    cudaGetSymbolAddress((void**)&p_cols_i, g_cols_i);
    cudaGetSymbolAddress((void**)&p_bs_u,   g_bsums_u);
    cudaGetSymbolAddress((void**)&p_bs_i,   g_bsums_i);

    const int TB = 256;
    const int EDGE_BLKS = (NEDGE + TB - 1) / TB;
    const int SCAN_BU = (NUSER + SB - 1) / SB;   // 98
    const int SCAN_BI = (NITEM + SB - 1) / SB;   // 49
    const int U_BLKS  = (NUSER * 16 + TB - 1) / TB;
    const int I_BLKS  = (NITEM * 16 + TB - 1) / TB;

    // ---- CSR build ----
    cudaMemsetAsync(p_cnt_u, 0, NUSER * sizeof(int), 0);
    cudaMemsetAsync(p_cnt_i, 0, NITEM * sizeof(int), 0);
    hist_degrees<<<EDGE_BLKS, TB>>>(u_idx, i_idx, p_cnt_u, p_cnt_i);
    compute_norms<<<(NUSER + TB - 1) / TB, TB>>>(p_cnt_u, p_nu_inv, p_nu_is, NUSER);
    compute_norms<<<(NITEM + TB - 1) / TB, TB>>>(p_cnt_i, p_ni_inv, p_ni_is, NITEM);

    scan_block<<<SCAN_BU, SB>>>(p_cnt_u, p_rp_u, p_bs_u, NUSER);
    scan_small<<<1, 128>>>(p_bs_u, SCAN_BU);
    add_offsets<<<SCAN_BU, SB>>>(p_rp_u, p_bs_u, NUSER);
    scan_block<<<SCAN_BI, SB>>>(p_cnt_i, p_rp_i, p_bs_i, NITEM);
    scan_small<<<1, 128>>>(p_bs_i, SCAN_BI);
    add_offsets<<<SCAN_BI, SB>>>(p_rp_i, p_bs_i, NITEM);

    cudaMemcpyAsync(p_cur_u, p_rp_u, NUSER * sizeof(int), cudaMemcpyDeviceToDevice, 0);
    cudaMemcpyAsync(p_cur_i, p_rp_i, NITEM * sizeof(int), cudaMemcpyDeviceToDevice, 0);
    fill_csr<<<EDGE_BLKS, TB>>>(u_idx, i_idx, p_cur_u, p_cur_i, p_cols_u, p_cols_i);

    // ---- init running sums ----
    cudaMemcpyAsync(sum_u, user_emb, NUSER * DIM * sizeof(float), cudaMemcpyDeviceToDevice, 0);
    cudaMemcpyAsync(sum_i, item_emb, NITEM * DIM * sizeof(float), cudaMemcpyDeviceToDevice, 0);

    for (int layer = 0; layer < NLAYERS; ++layer) {
        const float4* ue = (layer == 0) ? (const float4*)user_emb : (const float4*)p_user_e;
        const float4* ie = (layer == 0) ? (const float4*)item_emb : (const float4*)p_item_e;

        // ---- user propagation ----
        // acc_i[i] = sum_{u in N(i)} nu_is[u] * user_e[u]
        spmm_pull<<<I_BLKS, TB>>>(ue, p_nu_is, p_rp_i, p_cols_i,
                                  nullptr, (float4*)p_acc_i, nullptr, NITEM);
        // user_e[u] = nu_is[u] * sum_{i in N(u)} ni_inv[i] * acc_i[i]; sum_u += user_e
        spmm_pull<<<U_BLKS, TB>>>((const float4*)p_acc_i, p_ni_inv, p_rp_u, p_cols_u,
                                  p_nu_is, (float4*)p_user_e, (float4*)sum_u, NUSER);

        // ---- item propagation ----
        // acc_u[u] = sum_{i in N(u)} ni_is[i] * item_e[i]
        spmm_pull<<<U_BLKS, TB>>>(ie, p_ni_is, p_rp_u, p_cols_u,
                                  nullptr, (float4*)p_acc_u, nullptr, NUSER);
        // item_e[i] = ni_is[i] * sum_{u in N(i)} nu_inv[u] * acc_u[u]; sum_i += item_e
        spmm_pull<<<I_BLKS, TB>>>((const float4*)p_acc_u, p_nu_inv, p_rp_i, p_cols_i,
                                  p_ni_is, (float4*)p_item_e, (float4*)sum_i, NITEM);
    }

    const int N4 = (NUSER + NITEM) * DIM / 4;
    final_scale<<<(N4 + TB - 1) / TB, TB>>>((float4*)out, N4);
}

// round 3
// speedup vs baseline: 3.2021x; 1.4287x over previous
#include <cuda_runtime.h>
#include <cuda_fp16.h>

#define NUSER 100000
#define NITEM 50000
#define NEDGE 2000000
#define DIM   64
#define NLAYERS 3
#define SB    1024

// ---------------- scratch (device globals) ----------------
// fp16 gather operands / intermediates (rows of 64 halves = 128B)
__device__ __half g_pu[NUSER * DIM];   // pre-scaled user operand (d_u^-1/2 * user_e)
__device__ __half g_pi[NITEM * DIM];   // pre-scaled item operand (d_i^-1/2 * item_e)
__device__ __half g_au[NUSER * DIM];   // phase-A output, user rows (d_u^-1 * R(pi))
__device__ __half g_ai[NITEM * DIM];   // phase-A output, item rows (d_i^-1 * RT(pu))
__device__ int    g_cnt_u[NUSER];
__device__ int    g_cnt_i[NITEM];
__device__ int    g_rowptr_u[NUSER + 1];
__device__ int    g_rowptr_i[NITEM + 1];
__device__ int    g_cur_u[NUSER];
__device__ int    g_cur_i[NITEM];
__device__ int    g_cols_u[NEDGE];     // user-row CSR: item neighbor ids
__device__ int    g_cols_i[NEDGE];     // item-row CSR: user neighbor ids
__device__ int    g_bsums_u[128];
__device__ int    g_bsums_i[128];
__device__ float  g_nu_inv[NUSER];
__device__ float  g_nu_is [NUSER];
__device__ float  g_ni_inv[NITEM];
__device__ float  g_ni_is [NITEM];

// ---------------- helpers ----------------
__device__ __forceinline__ uint2 pack4h(float4 v) {
    __half2 a = __floats2half2_rn(v.x, v.y);
    __half2 b = __floats2half2_rn(v.z, v.w);
    uint2 r;
    r.x = *reinterpret_cast<unsigned*>(&a);
    r.y = *reinterpret_cast<unsigned*>(&b);
    return r;
}

// gather-add over one CSR row: 16 lanes per row, 8B (4 halves) per lane.
// fp32 accumulation. Pure adds — all scales pre-folded by producers.
__device__ __forceinline__ float4 gather_row(const uint2* __restrict__ src,
                                             const int*   __restrict__ cols,
                                             int beg, int end, int c, unsigned hmask) {
    float4 acc = make_float4(0.f, 0.f, 0.f, 0.f);
    for (int base = beg; base < end; base += 16) {
        int myi = base + c;
        int mycol = (myi < end) ? __ldg(cols + myi) : 0;
        int cnt = min(16, end - base);
        #pragma unroll 4
        for (int j = 0; j < cnt; ++j) {
            int col = __shfl_sync(hmask, mycol, j, 16);
            uint2 v = __ldg(src + col * 16 + c);
            __half2 h0 = *reinterpret_cast<__half2*>(&v.x);
            __half2 h1 = *reinterpret_cast<__half2*>(&v.y);
            float2 f0 = __half22float2(h0);
            float2 f1 = __half22float2(h1);
            acc.x += f0.x; acc.y += f0.y; acc.z += f1.x; acc.w += f1.y;
        }
    }
    return acc;
}

// ---------------- CSR build ----------------
__global__ void hist_degrees(const int* __restrict__ u_idx,
                             const int* __restrict__ i_idx,
                             int* __restrict__ cnt_u, int* __restrict__ cnt_i) {
    int t = blockIdx.x * blockDim.x + threadIdx.x;
    if (t >= NEDGE) return;
    atomicAdd(cnt_u + __ldg(u_idx + t), 1);
    atomicAdd(cnt_i + __ldg(i_idx + t), 1);
}

__global__ void scan_block(const int* __restrict__ in, int* __restrict__ out,
                           int* __restrict__ bsums, int n) {
    __shared__ int sh[SB];
    int gid = blockIdx.x * SB + threadIdx.x;
    int v = (gid < n) ? in[gid] : 0;
    sh[threadIdx.x] = v;
    __syncthreads();
    for (int off = 1; off < SB; off <<= 1) {
        int t = (threadIdx.x >= off) ? sh[threadIdx.x - off] : 0;
        __syncthreads();
        sh[threadIdx.x] += t;
        __syncthreads();
    }
    if (gid < n) out[gid] = sh[threadIdx.x] - v;
    if (threadIdx.x == SB - 1) bsums[blockIdx.x] = sh[SB - 1];
}

__global__ void scan_small(int* __restrict__ data, int n) {
    __shared__ int sh[128];
    int v = (threadIdx.x < n) ? data[threadIdx.x] : 0;
    sh[threadIdx.x] = v;
    __syncthreads();
    for (int off = 1; off < 128; off <<= 1) {
        int t = (threadIdx.x >= off) ? sh[threadIdx.x - off] : 0;
        __syncthreads();
        sh[threadIdx.x] += t;
        __syncthreads();
    }
    if (threadIdx.x < n) data[threadIdx.x] = sh[threadIdx.x] - v;
}

__global__ void add_offsets(int* __restrict__ out, const int* __restrict__ bsums, int n) {
    int gid = blockIdx.x * SB + threadIdx.x;
    if (gid < n) out[gid] += bsums[blockIdx.x];
    if (gid == 0) out[n] = NEDGE;
}

__global__ void fill_csr(const int* __restrict__ u_idx, const int* __restrict__ i_idx,
                         int* __restrict__ cur_u, int* __restrict__ cur_i,
                         int* __restrict__ cols_u, int* __restrict__ cols_i) {
    int e = blockIdx.x * blockDim.x + threadIdx.x;
    if (e >= NEDGE) return;
    int u = __ldg(u_idx + e);
    int i = __ldg(i_idx + e);
    cols_u[atomicAdd(cur_u + u, 1)] = i;
    cols_i[atomicAdd(cur_i + i, 1)] = u;
}

__global__ void compute_norms(const int* __restrict__ cnt,
                              float* __restrict__ inv, float* __restrict__ invsqrt, int n) {
    int t = blockIdx.x * blockDim.x + threadIdx.x;
    if (t >= n) return;
    float d = (float)cnt[t];
    d = (d == 0.0f) ? 1.0f : d;
    inv[t]     = 1.0f / d;
    invsqrt[t] = rsqrtf(d);
}

// ---------------- prescale: P = d^-1/2 * emb  (fp32 -> fp16) ----------------
__global__ void prescale(const float4* __restrict__ ue, const float4* __restrict__ ie,
                         const float* __restrict__ nu_is, const float* __restrict__ ni_is,
                         uint2* __restrict__ pu, uint2* __restrict__ pi) {
    int t = blockIdx.x * blockDim.x + threadIdx.x;
    if (t >= (NUSER + NITEM) * 16) return;
    if (t < NUSER * 16) {
        float s = __ldg(nu_is + (t >> 4));
        float4 v = __ldg(ue + t);
        v.x *= s; v.y *= s; v.z *= s; v.w *= s;
        pu[t] = pack4h(v);
    } else {
        int tt = t - NUSER * 16;
        float s = __ldg(ni_is + (tt >> 4));
        float4 v = __ldg(ie + tt);
        v.x *= s; v.y *= s; v.z *= s; v.w *= s;
        pi[tt] = pack4h(v);
    }
}

// ---------------- phase A: ai = d_i^-1 * RT(pu);  au = d_u^-1 * R(pi) ----------------
__global__ void __launch_bounds__(256)
phaseA(const uint2* __restrict__ pu, const uint2* __restrict__ pi,
       const int* __restrict__ rp_i, const int* __restrict__ cols_i,
       const int* __restrict__ rp_u, const int* __restrict__ cols_u,
       const float* __restrict__ ni_inv, const float* __restrict__ nu_inv,
       uint2* __restrict__ ai, uint2* __restrict__ au) {
    int t = blockIdx.x * blockDim.x + threadIdx.x;
    int r = t >> 4;
    if (r >= NITEM + NUSER) return;
    int c = t & 15;
    unsigned hmask = 0xFFFFu << (threadIdx.x & 16);
    if (r < NITEM) {
        float4 acc = gather_row(pu, cols_i, __ldg(rp_i + r), __ldg(rp_i + r + 1), c, hmask);
        float s = __ldg(ni_inv + r);
        acc.x *= s; acc.y *= s; acc.z *= s; acc.w *= s;
        ai[r * 16 + c] = pack4h(acc);
    } else {
        int u = r - NITEM;
        float4 acc = gather_row(pi, cols_u, __ldg(rp_u + u), __ldg(rp_u + u + 1), c, hmask);
        float s = __ldg(nu_inv + u);
        acc.x *= s; acc.y *= s; acc.z *= s; acc.w *= s;
        au[u * 16 + c] = pack4h(acc);
    }
}

// ---------------- phase B: S_u = R(ai), S_i = RT(au); sums + next operands ----------------
// sum_out = (base + d^-1/2 * S) [* 0.25 on last layer];  pre_out = d^-1 * S (skipped on last)
__global__ void __launch_bounds__(256)
phaseB(const uint2* __restrict__ ai, const uint2* __restrict__ au,
       const int* __restrict__ rp_u, const int* __restrict__ cols_u,
       const int* __restrict__ rp_i, const int* __restrict__ cols_i,
       const float* __restrict__ nu_is, const float* __restrict__ nu_inv,
       const float* __restrict__ ni_is, const float* __restrict__ ni_inv,
       const float4* __restrict__ emb_u, const float4* __restrict__ emb_i,
       float4* __restrict__ sum_u, float4* __restrict__ sum_i,
       uint2* __restrict__ pu, uint2* __restrict__ pi,
       int layer0, int last) {
    int t = blockIdx.x * blockDim.x + threadIdx.x;
    int r = t >> 4;
    if (r >= NITEM + NUSER) return;
    int c = t & 15;
    unsigned hmask = 0xFFFFu << (threadIdx.x & 16);
    const float k = 1.0f / (NLAYERS + 1);
    if (r < NUSER) {
        int idx = r * 16 + c;
        float4 S = gather_row(ai, cols_u, __ldg(rp_u + r), __ldg(rp_u + r + 1), c, hmask);
        float sis = __ldg(nu_is + r);
        float4 base = layer0 ? __ldg(emb_u + idx) : sum_u[idx];
        float4 ns;
        ns.x = base.x + sis * S.x; ns.y = base.y + sis * S.y;
        ns.z = base.z + sis * S.z; ns.w = base.w + sis * S.w;
        if (last) { ns.x *= k; ns.y *= k; ns.z *= k; ns.w *= k; }
        sum_u[idx] = ns;
        if (!last) {
            float si = __ldg(nu_inv + r);
            float4 p; p.x = si * S.x; p.y = si * S.y; p.z = si * S.z; p.w = si * S.w;
            pu[idx] = pack4h(p);
        }
    } else {
        int i = r - NUSER;
        int idx = i * 16 + c;
        float4 S = gather_row(au, cols_i, __ldg(rp_i + i), __ldg(rp_i + i + 1), c, hmask);
        float sis = __ldg(ni_is + i);
        float4 base = layer0 ? __ldg(emb_i + idx) : sum_i[idx];
        float4 ns;
        ns.x = base.x + sis * S.x; ns.y = base.y + sis * S.y;
        ns.z = base.z + sis * S.z; ns.w = base.w + sis * S.w;
        if (last) { ns.x *= k; ns.y *= k; ns.z *= k; ns.w *= k; }
        sum_i[idx] = ns;
        if (!last) {
            float si = __ldg(ni_inv + i);
            float4 p; p.x = si * S.x; p.y = si * S.y; p.z = si * S.z; p.w = si * S.w;
            pi[idx] = pack4h(p);
        }
    }
}

// ---------------- launch ----------------
extern "C" void kernel_launch(void* const* d_in, const int* in_sizes, int n_in,
                              void* d_out, int out_size) {
    const float* user_emb = (const float*)d_in[0];
    const float* item_emb = (const float*)d_in[1];
    const int*   u_idx    = (const int*)d_in[2];
    const int*   i_idx    = (const int*)d_in[3];
    float* out = (float*)d_out;
    float* sum_u = out;
    float* sum_i = out + NUSER * DIM;

    __half *p_pu, *p_pi, *p_au, *p_ai;
    float *p_nu_inv, *p_nu_is, *p_ni_inv, *p_ni_is;
    int *p_cnt_u, *p_cnt_i, *p_rp_u, *p_rp_i, *p_cur_u, *p_cur_i;
    int *p_cols_u, *p_cols_i, *p_bs_u, *p_bs_i;
    cudaGetSymbolAddress((void**)&p_pu, g_pu);
    cudaGetSymbolAddress((void**)&p_pi, g_pi);
    cudaGetSymbolAddress((void**)&p_au, g_au);
    cudaGetSymbolAddress((void**)&p_ai, g_ai);
    cudaGetSymbolAddress((void**)&p_nu_inv, g_nu_inv);
    cudaGetSymbolAddress((void**)&p_nu_is,  g_nu_is);
    cudaGetSymbolAddress((void**)&p_ni_inv, g_ni_inv);
    cudaGetSymbolAddress((void**)&p_ni_is,  g_ni_is);
    cudaGetSymbolAddress((void**)&p_cnt_u,  g_cnt_u);
    cudaGetSymbolAddress((void**)&p_cnt_i,  g_cnt_i);
    cudaGetSymbolAddress((void**)&p_rp_u,   g_rowptr_u);
    cudaGetSymbolAddress((void**)&p_rp_i,   g_rowptr_i);
    cudaGetSymbolAddress((void**)&p_cur_u,  g_cur_u);
    cudaGetSymbolAddress((void**)&p_cur_i,  g_cur_i);
    cudaGetSymbolAddress((void**)&p_cols_u, g_cols_u);
    cudaGetSymbolAddress((void**)&p_cols_i, g_cols_i);
    cudaGetSymbolAddress((void**)&p_bs_u,   g_bsums_u);
    cudaGetSymbolAddress((void**)&p_bs_i,   g_bsums_i);

    const int TB = 256;
    const int EDGE_BLKS = (NEDGE + TB - 1) / TB;
    const int SCAN_BU = (NUSER + SB - 1) / SB;
    const int SCAN_BI = (NITEM + SB - 1) / SB;
    const int ALL_BLKS = ((NUSER + NITEM) * 16 + TB - 1) / TB;

    // ---- CSR build + norms ----
    cudaMemsetAsync(p_cnt_u, 0, NUSER * sizeof(int), 0);
    cudaMemsetAsync(p_cnt_i, 0, NITEM * sizeof(int), 0);
    hist_degrees<<<EDGE_BLKS, TB>>>(u_idx, i_idx, p_cnt_u, p_cnt_i);
    compute_norms<<<(NUSER + TB - 1) / TB, TB>>>(p_cnt_u, p_nu_inv, p_nu_is, NUSER);
    compute_norms<<<(NITEM + TB - 1) / TB, TB>>>(p_cnt_i, p_ni_inv, p_ni_is, NITEM);
    scan_block<<<SCAN_BU, SB>>>(p_cnt_u, p_rp_u, p_bs_u, NUSER);
    scan_small<<<1, 128>>>(p_bs_u, SCAN_BU);
    add_offsets<<<SCAN_BU, SB>>>(p_rp_u, p_bs_u, NUSER);
    scan_block<<<SCAN_BI, SB>>>(p_cnt_i, p_rp_i, p_bs_i, NITEM);
    scan_small<<<1, 128>>>(p_bs_i, SCAN_BI);
    add_offsets<<<SCAN_BI, SB>>>(p_rp_i, p_bs_i, NITEM);
    cudaMemcpyAsync(p_cur_u, p_rp_u, NUSER * sizeof(int), cudaMemcpyDeviceToDevice, 0);
    cudaMemcpyAsync(p_cur_i, p_rp_i, NITEM * sizeof(int), cudaMemcpyDeviceToDevice, 0);
    fill_csr<<<EDGE_BLKS, TB>>>(u_idx, i_idx, p_cur_u, p_cur_i, p_cols_u, p_cols_i);

    // ---- initial pre-scaled operands ----
    prescale<<<ALL_BLKS, TB>>>((const float4*)user_emb, (const float4*)item_emb,
                               p_nu_is, p_ni_is, (uint2*)p_pu, (uint2*)p_pi);

    // ---- layers ----
    for (int layer = 0; layer < NLAYERS; ++layer) {
        phaseA<<<ALL_BLKS, TB>>>((const uint2*)p_pu, (const uint2*)p_pi,
                                 p_rp_i, p_cols_i, p_rp_u, p_cols_u,
                                 p_ni_inv, p_nu_inv, (uint2*)p_ai, (uint2*)p_au);
        phaseB<<<ALL_BLKS, TB>>>((const uint2*)p_ai, (const uint2*)p_au,
                                 p_rp_u, p_cols_u, p_rp_i, p_cols_i,
                                 p_nu_is, p_nu_inv, p_ni_is, p_ni_inv,
                                 (const float4*)user_emb, (const float4*)item_emb,
                                 (float4*)sum_u, (float4*)sum_i,
                                 (uint2*)p_pu, (uint2*)p_pi,
                                 layer == 0 ? 1 : 0, layer == NLAYERS - 1 ? 1 : 0);
    }
}